// round 1
// baseline (speedup 1.0000x reference)
#include <cuda_runtime.h>
#include <math.h>

#define BATCH  4
#define CH     256
#define NGROUP 32
#define HW     4096
#define GEPS   1e-6f

// ---------------- scratch (device globals; no allocation allowed) -------------
__device__ float g_of[(size_t)BATCH * CH * HW];   // group-normed activations [b][c][i]
__device__ float g_q [(size_t)BATCH * CH * HW];   // Q^T  [b][c][i]
__device__ float g_k [(size_t)BATCH * CH * HW];   // K    [b][c][i]
__device__ float g_v [(size_t)BATCH * CH * HW];   // V    [b][c][i]
__device__ float g_at[(size_t)BATCH * CH * HW];   // attn output [b][c][i]
__device__ float g_w [(size_t)BATCH * HW * HW];   // scores / probs [b][i][j]  (268 MB)
__device__ float g_mean[BATCH * NGROUP];
__device__ float g_rstd[BATCH * NGROUP];

// ---------------- GroupNorm: stats --------------------------------------------
// One block per (b, group). Group channels are contiguous: 8*4096 = 32768 floats.
__global__ void __launch_bounds__(256) gn_stats(const float* __restrict__ x) {
    const int bg = blockIdx.x;                       // b*NGROUP + g
    const float* p = x + (size_t)bg * (CH / NGROUP) * HW;
    const int tid = threadIdx.x;

    float s = 0.f, s2 = 0.f;
    const int n4 = (CH / NGROUP) * HW / 4;           // 8192 float4
    for (int i = tid; i < n4; i += 256) {
        float4 v = ((const float4*)p)[i];
        s  += v.x + v.y + v.z + v.w;
        s2 += v.x * v.x + v.y * v.y + v.z * v.z + v.w * v.w;
    }
    __shared__ float red[64];
    #pragma unroll
    for (int o = 16; o; o >>= 1) {
        s  += __shfl_xor_sync(0xffffffffu, s,  o);
        s2 += __shfl_xor_sync(0xffffffffu, s2, o);
    }
    if ((tid & 31) == 0) { red[tid >> 5] = s; red[32 + (tid >> 5)] = s2; }
    __syncthreads();
    if (tid == 0) {
        float ts = 0.f, ts2 = 0.f;
        #pragma unroll
        for (int w = 0; w < 8; w++) { ts += red[w]; ts2 += red[32 + w]; }
        const float inv_n = 1.0f / ((CH / NGROUP) * HW);
        float mean = ts * inv_n;
        float var  = ts2 * inv_n - mean * mean;
        g_mean[bg] = mean;
        g_rstd[bg] = rsqrtf(var + GEPS);
    }
}

// ---------------- GroupNorm: apply --------------------------------------------
__global__ void __launch_bounds__(256) gn_apply(const float* __restrict__ x,
                                                const float* __restrict__ gs,
                                                const float* __restrict__ gb) {
    size_t i4 = (size_t)blockIdx.x * blockDim.x + threadIdx.x;
    const size_t total4 = (size_t)BATCH * CH * HW / 4;
    if (i4 >= total4) return;
    size_t idx = i4 * 4;
    int c  = (int)((idx / HW) % CH);
    int bg = (int)(idx / ((CH / NGROUP) * HW));      // b*NGROUP+g (contiguous groups)
    float r = g_rstd[bg];
    float a = gs[c] * r;
    float t = gb[c] - g_mean[bg] * a;
    float4 v = ((const float4*)x)[i4];
    float4 o;
    o.x = v.x * a + t; o.y = v.y * a + t; o.z = v.z * a + t; o.w = v.w * a + t;
    ((float4*)g_of)[i4] = o;
}

// ---------------- generic 128x128x8 SGEMM --------------------------------------
// D[m,n] = scale * sum_k a(m,k)*b(k,n) + bias[m] + resid[m,n]
// AK=true : A is [M,K] row-major (k contiguous). AK=false: A is [K,M] (m contiguous).
// BK=false: B is [K,N] row-major (n contiguous). BK=true : B is [N,K] (k contiguous).
// M,N multiples of 128; K multiple of 8. blockDim = 256.
template<bool AK, bool BK>
__global__ void __launch_bounds__(256) gemm128(
    const float* __restrict__ A, const float* __restrict__ B,
    float* __restrict__ D, int M, int N, int K,
    long long sA, long long sB, long long sD,
    const float* __restrict__ bias, float scale,
    const float* __restrict__ resid)
{
    __shared__ float As[8][128];
    __shared__ float Bs[8][128];
    const int bz = blockIdx.z;
    A += (size_t)bz * sA;
    B += (size_t)bz * sB;
    D += (size_t)bz * sD;
    const float* R = resid ? resid + (size_t)bz * sD : nullptr;

    const int m0 = blockIdx.y * 128, n0 = blockIdx.x * 128;
    const int tid = threadIdx.x;
    const int tx = tid & 15, ty = tid >> 4;

    float acc[8][8] = {};

    for (int k0 = 0; k0 < K; k0 += 8) {
        if (AK) {
            int mm = tid >> 1, kk = (tid & 1) * 4;
            float4 a = *(const float4*)(A + (size_t)(m0 + mm) * K + k0 + kk);
            As[kk + 0][mm] = a.x; As[kk + 1][mm] = a.y;
            As[kk + 2][mm] = a.z; As[kk + 3][mm] = a.w;
        } else {
            int kk = tid >> 5, mm = (tid & 31) << 2;
            *(float4*)(&As[kk][mm]) = *(const float4*)(A + (size_t)(k0 + kk) * M + m0 + mm);
        }
        if (BK) {
            int nn = tid >> 1, kk = (tid & 1) * 4;
            float4 b = *(const float4*)(B + (size_t)(n0 + nn) * K + k0 + kk);
            Bs[kk + 0][nn] = b.x; Bs[kk + 1][nn] = b.y;
            Bs[kk + 2][nn] = b.z; Bs[kk + 3][nn] = b.w;
        } else {
            int kk = tid >> 5, nn = (tid & 31) << 2;
            *(float4*)(&Bs[kk][nn]) = *(const float4*)(B + (size_t)(k0 + kk) * N + n0 + nn);
        }
        __syncthreads();

        #pragma unroll
        for (int kk = 0; kk < 8; kk++) {
            float a[8], b[8];
            *(float4*)(a)     = *(const float4*)(&As[kk][ty * 8]);
            *(float4*)(a + 4) = *(const float4*)(&As[kk][ty * 8 + 4]);
            *(float4*)(b)     = *(const float4*)(&Bs[kk][tx * 8]);
            *(float4*)(b + 4) = *(const float4*)(&Bs[kk][tx * 8 + 4]);
            #pragma unroll
            for (int i = 0; i < 8; i++)
                #pragma unroll
                for (int j = 0; j < 8; j++)
                    acc[i][j] = fmaf(a[i], b[j], acc[i][j]);
        }
        __syncthreads();
    }

    #pragma unroll
    for (int i = 0; i < 8; i++) {
        int m = m0 + ty * 8 + i;
        float bv = bias ? bias[m] : 0.0f;
        size_t row = (size_t)m * N + n0 + tx * 8;
        #pragma unroll
        for (int j = 0; j < 8; j += 4) {
            float4 o;
            o.x = acc[i][j + 0] * scale + bv;
            o.y = acc[i][j + 1] * scale + bv;
            o.z = acc[i][j + 2] * scale + bv;
            o.w = acc[i][j + 3] * scale + bv;
            if (R) {
                float4 rr = *(const float4*)(R + row + j);
                o.x += rr.x; o.y += rr.y; o.z += rr.z; o.w += rr.w;
            }
            *(float4*)(D + row + j) = o;
        }
    }
}

// ---------------- row softmax over g_w (in place) -------------------------------
// One block per (row i, batch b); 4096 floats held in 16 regs/thread.
__global__ void __launch_bounds__(256) softmax_rows() {
    const int i = blockIdx.x, b = blockIdx.y;
    float* p = g_w + ((size_t)b * HW + i) * HW;
    const int tid = threadIdx.x;
    __shared__ float red[32];

    float vals[16];
    float mx = -INFINITY;
    #pragma unroll
    for (int t = 0; t < 16; t++) { vals[t] = p[t * 256 + tid]; mx = fmaxf(mx, vals[t]); }
    #pragma unroll
    for (int o = 16; o; o >>= 1) mx = fmaxf(mx, __shfl_xor_sync(0xffffffffu, mx, o));
    if ((tid & 31) == 0) red[tid >> 5] = mx;
    __syncthreads();
    mx = red[0];
    #pragma unroll
    for (int w = 1; w < 8; w++) mx = fmaxf(mx, red[w]);
    __syncthreads();                                  // done reading red before reuse

    float s = 0.f;
    #pragma unroll
    for (int t = 0; t < 16; t++) { vals[t] = __expf(vals[t] - mx); s += vals[t]; }
    #pragma unroll
    for (int o = 16; o; o >>= 1) s += __shfl_xor_sync(0xffffffffu, s, o);
    if ((tid & 31) == 0) red[tid >> 5] = s;
    __syncthreads();
    s = 0.f;
    #pragma unroll
    for (int w = 0; w < 8; w++) s += red[w];
    float inv = 1.0f / s;
    #pragma unroll
    for (int t = 0; t < 16; t++) p[t * 256 + tid] = vals[t] * inv;
}

// ---------------- launch --------------------------------------------------------
extern "C" void kernel_launch(void* const* d_in, const int* in_sizes, int n_in,
                              void* d_out, int out_size) {
    const float* x  = (const float*)d_in[0];
    const float* gs = (const float*)d_in[1];
    const float* gb = (const float*)d_in[2];
    const float* wq = (const float*)d_in[3];
    const float* bq = (const float*)d_in[4];
    const float* wk = (const float*)d_in[5];
    const float* bk = (const float*)d_in[6];
    const float* wv = (const float*)d_in[7];
    const float* bv = (const float*)d_in[8];
    const float* wp = (const float*)d_in[9];
    const float* bp = (const float*)d_in[10];
    float* out = (float*)d_out;

    float *p_of, *p_q, *p_k, *p_v, *p_at, *p_w;
    cudaGetSymbolAddress((void**)&p_of, g_of);
    cudaGetSymbolAddress((void**)&p_q,  g_q);
    cudaGetSymbolAddress((void**)&p_k,  g_k);
    cudaGetSymbolAddress((void**)&p_v,  g_v);
    cudaGetSymbolAddress((void**)&p_at, g_at);
    cudaGetSymbolAddress((void**)&p_w,  g_w);

    const long long sAct = (long long)CH * HW;   // per-batch activation stride
    const long long sW   = (long long)HW * HW;   // per-batch score stride

    // 1) GroupNorm
    gn_stats<<<BATCH * NGROUP, 256>>>(x);
    gn_apply<<<(BATCH * CH * HW / 4 + 255) / 256, 256>>>(x, gs, gb);

    // 2) Q/K/V projections: [256,256] x [256,4096] per batch, output channel-major
    dim3 gQKV(HW / 128, CH / 128, BATCH);
    gemm128<true,  false><<<gQKV, 256>>>(wq, p_of, p_q, CH, HW, CH, 0, sAct, sAct, bq, 1.0f, nullptr);
    gemm128<true,  false><<<gQKV, 256>>>(wk, p_of, p_k, CH, HW, CH, 0, sAct, sAct, bk, 1.0f, nullptr);
    gemm128<true,  false><<<gQKV, 256>>>(wv, p_of, p_v, CH, HW, CH, 0, sAct, sAct, bv, 1.0f, nullptr);

    // 3) scores: w[i,j] = (1/16) * sum_c Q^T[c,i] * K[c,j]   (TN: both operands m/n-contiguous)
    dim3 gS(HW / 128, HW / 128, BATCH);
    gemm128<false, false><<<gS, 256>>>(p_q, p_k, p_w, HW, HW, CH, sAct, sAct, sW, nullptr, 0.0625f, nullptr);

    // 4) softmax over j (in place)
    softmax_rows<<<dim3(HW, BATCH), 256>>>();

    // 5) attn: out[c,i] = sum_j V[c,j] * P[i,j]   (NT: both operands k-contiguous)
    dim3 gA(HW / 128, CH / 128, BATCH);
    gemm128<true,  true ><<<gA, 256>>>(p_v, p_w, p_at, CH, HW, HW, sAct, sW, sAct, nullptr, 1.0f, nullptr);

    // 6) proj + bias + residual -> d_out
    gemm128<true,  false><<<gQKV, 256>>>(wp, p_at, out, CH, HW, CH, 0, sAct, sAct, bp, 1.0f, x);
}

// round 2
// speedup vs baseline: 3.7640x; 3.7640x over previous
#include <cuda_runtime.h>
#include <cuda_bf16.h>
#include <math.h>

#define BATCH  4
#define CH     256
#define NGROUP 32
#define HW     4096
#define GEPS   1e-6f

// ---------------- scratch (device globals; no allocation allowed) -------------
__device__ float         g_of [(size_t)BATCH * CH * HW];   // group-normed [b][c][i] fp32
__device__ __nv_bfloat16 g_qT [(size_t)BATCH * HW * CH];   // Q  [b][i][c] bf16
__device__ __nv_bfloat16 g_kT [(size_t)BATCH * HW * CH];   // K  [b][j][c] bf16
__device__ __nv_bfloat16 g_v16[(size_t)BATCH * CH * HW];   // V  [b][c][j] bf16
__device__ float         g_w  [(size_t)BATCH * HW * HW];   // scores fp32 (268 MB)
__device__ __nv_bfloat16 g_p  [(size_t)BATCH * HW * HW];   // probs bf16 (134 MB)
__device__ float         g_at [(size_t)BATCH * CH * HW];   // attn out [b][c][i] fp32
__device__ float g_mean[BATCH * NGROUP];
__device__ float g_rstd[BATCH * NGROUP];

// ---------------- GroupNorm: stats --------------------------------------------
__global__ void __launch_bounds__(256) gn_stats(const float* __restrict__ x) {
    const int bg = blockIdx.x;
    const float* p = x + (size_t)bg * (CH / NGROUP) * HW;
    const int tid = threadIdx.x;

    float s = 0.f, s2 = 0.f;
    const int n4 = (CH / NGROUP) * HW / 4;
    for (int i = tid; i < n4; i += 256) {
        float4 v = ((const float4*)p)[i];
        s  += v.x + v.y + v.z + v.w;
        s2 += v.x * v.x + v.y * v.y + v.z * v.z + v.w * v.w;
    }
    __shared__ float red[64];
    #pragma unroll
    for (int o = 16; o; o >>= 1) {
        s  += __shfl_xor_sync(0xffffffffu, s,  o);
        s2 += __shfl_xor_sync(0xffffffffu, s2, o);
    }
    if ((tid & 31) == 0) { red[tid >> 5] = s; red[32 + (tid >> 5)] = s2; }
    __syncthreads();
    if (tid == 0) {
        float ts = 0.f, ts2 = 0.f;
        #pragma unroll
        for (int w = 0; w < 8; w++) { ts += red[w]; ts2 += red[32 + w]; }
        const float inv_n = 1.0f / ((CH / NGROUP) * HW);
        float mean = ts * inv_n;
        float var  = ts2 * inv_n - mean * mean;
        g_mean[bg] = mean;
        g_rstd[bg] = rsqrtf(var + GEPS);
    }
}

// ---------------- GroupNorm: apply --------------------------------------------
__global__ void __launch_bounds__(256) gn_apply(const float* __restrict__ x,
                                                const float* __restrict__ gs,
                                                const float* __restrict__ gb) {
    size_t i4 = (size_t)blockIdx.x * blockDim.x + threadIdx.x;
    const size_t total4 = (size_t)BATCH * CH * HW / 4;
    if (i4 >= total4) return;
    size_t idx = i4 * 4;
    int c  = (int)((idx / HW) % CH);
    int bg = (int)(idx / ((CH / NGROUP) * HW));
    float r = g_rstd[bg];
    float a = gs[c] * r;
    float t = gb[c] - g_mean[bg] * a;
    float4 v = ((const float4*)x)[i4];
    float4 o;
    o.x = v.x * a + t; o.y = v.y * a + t; o.z = v.z * a + t; o.w = v.w * a + t;
    ((float4*)g_of)[i4] = o;
}

// ---------------- generic 128x128x8 SGEMM (fp32 SIMT) ---------------------------
// OMODE 0: fp32 out [m][n] (+resid). OMODE 1: bf16 out [m][n]. OMODE 2: bf16 out [n][m].
template<bool AK, bool BK, int OMODE>
__global__ void __launch_bounds__(256) gemm128(
    const float* __restrict__ A, const float* __restrict__ B,
    void* __restrict__ Dv, int M, int N, int K,
    long long sA, long long sB, long long sD,
    const float* __restrict__ bias, float scale,
    const float* __restrict__ resid)
{
    __shared__ float As[8][128];
    __shared__ float Bs[8][128];
    const int bz = blockIdx.z;
    A += (size_t)bz * sA;
    B += (size_t)bz * sB;

    const int m0 = blockIdx.y * 128, n0 = blockIdx.x * 128;
    const int tid = threadIdx.x;
    const int tx = tid & 15, ty = tid >> 4;

    float acc[8][8] = {};

    for (int k0 = 0; k0 < K; k0 += 8) {
        if (AK) {
            int mm = tid >> 1, kk = (tid & 1) * 4;
            float4 a = *(const float4*)(A + (size_t)(m0 + mm) * K + k0 + kk);
            As[kk + 0][mm] = a.x; As[kk + 1][mm] = a.y;
            As[kk + 2][mm] = a.z; As[kk + 3][mm] = a.w;
        } else {
            int kk = tid >> 5, mm = (tid & 31) << 2;
            *(float4*)(&As[kk][mm]) = *(const float4*)(A + (size_t)(k0 + kk) * M + m0 + mm);
        }
        if (BK) {
            int nn = tid >> 1, kk = (tid & 1) * 4;
            float4 b = *(const float4*)(B + (size_t)(n0 + nn) * K + k0 + kk);
            Bs[kk + 0][nn] = b.x; Bs[kk + 1][nn] = b.y;
            Bs[kk + 2][nn] = b.z; Bs[kk + 3][nn] = b.w;
        } else {
            int kk = tid >> 5, nn = (tid & 31) << 2;
            *(float4*)(&Bs[kk][nn]) = *(const float4*)(B + (size_t)(k0 + kk) * N + n0 + nn);
        }
        __syncthreads();

        #pragma unroll
        for (int kk = 0; kk < 8; kk++) {
            float a[8], b[8];
            *(float4*)(a)     = *(const float4*)(&As[kk][ty * 8]);
            *(float4*)(a + 4) = *(const float4*)(&As[kk][ty * 8 + 4]);
            *(float4*)(b)     = *(const float4*)(&Bs[kk][tx * 8]);
            *(float4*)(b + 4) = *(const float4*)(&Bs[kk][tx * 8 + 4]);
            #pragma unroll
            for (int i = 0; i < 8; i++)
                #pragma unroll
                for (int j = 0; j < 8; j++)
                    acc[i][j] = fmaf(a[i], b[j], acc[i][j]);
        }
        __syncthreads();
    }

    if (OMODE == 0) {
        float* D = (float*)Dv + (size_t)bz * sD;
        const float* R = resid ? resid + (size_t)bz * sD : nullptr;
        #pragma unroll
        for (int i = 0; i < 8; i++) {
            int m = m0 + ty * 8 + i;
            float bv = bias ? bias[m] : 0.0f;
            size_t row = (size_t)m * N + n0 + tx * 8;
            #pragma unroll
            for (int j = 0; j < 8; j += 4) {
                float4 o;
                o.x = acc[i][j + 0] * scale + bv;
                o.y = acc[i][j + 1] * scale + bv;
                o.z = acc[i][j + 2] * scale + bv;
                o.w = acc[i][j + 3] * scale + bv;
                if (R) {
                    float4 rr = *(const float4*)(R + row + j);
                    o.x += rr.x; o.y += rr.y; o.z += rr.z; o.w += rr.w;
                }
                *(float4*)(D + row + j) = o;
            }
        }
    } else if (OMODE == 1) {
        __nv_bfloat16* D = (__nv_bfloat16*)Dv + (size_t)bz * sD;
        #pragma unroll
        for (int i = 0; i < 8; i++) {
            int m = m0 + ty * 8 + i;
            float bv = bias ? bias[m] : 0.0f;
            __nv_bfloat16 tmp[8];
            #pragma unroll
            for (int j = 0; j < 8; j++)
                tmp[j] = __float2bfloat16_rn(acc[i][j] * scale + bv);
            *(uint4*)(&D[(size_t)m * N + n0 + tx * 8]) = *(uint4*)tmp;
        }
    } else {
        __nv_bfloat16* D = (__nv_bfloat16*)Dv + (size_t)bz * sD;
        float bvs[8];
        #pragma unroll
        for (int i = 0; i < 8; i++)
            bvs[i] = bias ? bias[m0 + ty * 8 + i] : 0.0f;
        #pragma unroll
        for (int j = 0; j < 8; j++) {
            int n = n0 + tx * 8 + j;
            __nv_bfloat16 tmp[8];
            #pragma unroll
            for (int i = 0; i < 8; i++)
                tmp[i] = __float2bfloat16_rn(acc[i][j] * scale + bvs[i]);
            *(uint4*)(&D[(size_t)n * M + m0 + ty * 8]) = *(uint4*)tmp;
        }
    }
}

// ---------------- bf16 tensor-core GEMM: D[m][n] = scale*sum_k A[m][k]*B[n][k] ----
// A: [M][K] bf16 k-contig, B: [N][K] bf16 k-contig, D: [M][N] fp32.
// CTA 128x128, BK=32, 8 warps (2m x 4n), warp tile 64x32, mma m16n8k16, cp.async 2-stage.

__device__ __forceinline__ unsigned swz(int m, int c) {  // 16B-chunk index in [128][32]bf16 tile
    return (unsigned)((m << 2) + (c ^ ((m >> 1) & 3)));
}

#define CP16(dst_u32, src_ptr) \
    asm volatile("cp.async.cg.shared.global [%0], [%1], 16;\n" :: "r"(dst_u32), "l"(src_ptr))
#define LDMX4(r0, r1, r2, r3, addr) \
    asm volatile("ldmatrix.sync.aligned.m8n8.x4.shared.b16 {%0,%1,%2,%3}, [%4];\n" \
                 : "=r"(r0), "=r"(r1), "=r"(r2), "=r"(r3) : "r"(addr))
#define MMA16816(c0, c1, c2, c3, a0, a1, a2, a3, b0, b1) \
    asm volatile("mma.sync.aligned.m16n8k16.row.col.f32.bf16.bf16.f32 " \
                 "{%0,%1,%2,%3}, {%4,%5,%6,%7}, {%8,%9}, {%0,%1,%2,%3};\n" \
                 : "+f"(c0), "+f"(c1), "+f"(c2), "+f"(c3) \
                 : "r"(a0), "r"(a1), "r"(a2), "r"(a3), "r"(b0), "r"(b1))

__global__ void __launch_bounds__(256) mma_gemm(
    const __nv_bfloat16* __restrict__ A, const __nv_bfloat16* __restrict__ B,
    float* __restrict__ D, int M, int N, int K,
    long long sA, long long sB, long long sD, float scale)
{
    __shared__ __align__(16) unsigned char sm[2 * 16384];   // [stage][A 8KB | B 8KB]
    const int bz = blockIdx.z;
    A += (size_t)bz * sA;
    B += (size_t)bz * sB;
    D += (size_t)bz * sD;
    const int m0 = blockIdx.y * 128, n0 = blockIdx.x * 128;
    const int tid = threadIdx.x, lane = tid & 31, warp = tid >> 5;
    const int wm = warp >> 2, wn = warp & 3;

    const unsigned smbase = (unsigned)__cvta_generic_to_shared(sm);

    // global-load assignment: thread -> (row tid>>2, chunk tid&3), two rows 64 apart
    const int lm = tid >> 2, lc = tid & 3;
    const __nv_bfloat16* gA0 = A + (size_t)(m0 + lm)      * K + lc * 8;
    const __nv_bfloat16* gA1 = A + (size_t)(m0 + lm + 64) * K + lc * 8;
    const __nv_bfloat16* gB0 = B + (size_t)(n0 + lm)      * K + lc * 8;
    const __nv_bfloat16* gB1 = B + (size_t)(n0 + lm + 64) * K + lc * 8;
    const unsigned dA0 = swz(lm, lc) * 16u;
    const unsigned dA1 = swz(lm + 64, lc) * 16u;
    const unsigned dB0 = 8192u + swz(lm, lc) * 16u;
    const unsigned dB1 = 8192u + swz(lm + 64, lc) * 16u;

    // ldmatrix offsets (within a 16KB stage), kstep toggles byte 32 via XOR
    unsigned aOff[4], bOff[2];
    {
        int r = wm * 64 + (lane & 15);
        int c0 = lane >> 4;
        #pragma unroll
        for (int mt = 0; mt < 4; mt++) aOff[mt] = swz(r + mt * 16, c0) * 16u;
    }
    {
        int r = wn * 32 + ((lane >> 4) << 3) + (lane & 7);
        int c0 = (lane >> 3) & 1;
        #pragma unroll
        for (int p = 0; p < 2; p++) bOff[p] = 8192u + swz(r + p * 16, c0) * 16u;
    }

    float acc[4][4][4];
    #pragma unroll
    for (int i = 0; i < 4; i++)
        #pragma unroll
        for (int j = 0; j < 4; j++)
            #pragma unroll
            for (int r = 0; r < 4; r++) acc[i][j][r] = 0.f;

    const int iters = K >> 5;

    // prologue: stage 0
    {
        unsigned s = smbase;
        CP16(s + dA0, gA0); CP16(s + dA1, gA1);
        CP16(s + dB0, gB0); CP16(s + dB1, gB1);
        asm volatile("cp.async.commit_group;\n");
    }

    for (int it = 0; it < iters; ++it) {
        const int cur = it & 1;
        if (it + 1 < iters) {
            unsigned s = smbase + (unsigned)(cur ^ 1) * 16384u;
            int k0 = (it + 1) << 5;
            CP16(s + dA0, gA0 + k0); CP16(s + dA1, gA1 + k0);
            CP16(s + dB0, gB0 + k0); CP16(s + dB1, gB1 + k0);
            asm volatile("cp.async.commit_group;\n");
            asm volatile("cp.async.wait_group 1;\n");
        } else {
            asm volatile("cp.async.wait_group 0;\n");
        }
        __syncthreads();

        const unsigned sb = smbase + (unsigned)cur * 16384u;
        #pragma unroll
        for (int ks = 0; ks < 2; ++ks) {
            const unsigned kx = (unsigned)ks * 32u;
            unsigned a[4][4], b[2][4];
            #pragma unroll
            for (int mt = 0; mt < 4; mt++)
                LDMX4(a[mt][0], a[mt][1], a[mt][2], a[mt][3], sb + (aOff[mt] ^ kx));
            #pragma unroll
            for (int p = 0; p < 2; p++)
                LDMX4(b[p][0], b[p][1], b[p][2], b[p][3], sb + (bOff[p] ^ kx));

            #pragma unroll
            for (int mt = 0; mt < 4; mt++) {
                #pragma unroll
                for (int nt = 0; nt < 4; nt++) {
                    const int p = nt >> 1, h = (nt & 1) << 1;
                    MMA16816(acc[mt][nt][0], acc[mt][nt][1], acc[mt][nt][2], acc[mt][nt][3],
                             a[mt][0], a[mt][1], a[mt][2], a[mt][3],
                             b[p][h + 0], b[p][h + 1]);
                }
            }
        }
        __syncthreads();
    }

    // epilogue
    const int row = m0 + wm * 64 + (lane >> 2);
    const int col = n0 + wn * 32 + (lane & 3) * 2;
    #pragma unroll
    for (int mt = 0; mt < 4; mt++) {
        #pragma unroll
        for (int nt = 0; nt < 4; nt++) {
            int r = row + mt * 16, cc = col + nt * 8;
            float2 v0 = { acc[mt][nt][0] * scale, acc[mt][nt][1] * scale };
            float2 v1 = { acc[mt][nt][2] * scale, acc[mt][nt][3] * scale };
            *(float2*)(&D[(size_t)r * N + cc])       = v0;
            *(float2*)(&D[(size_t)(r + 8) * N + cc]) = v1;
        }
    }
}

// ---------------- row softmax: fp32 scores -> bf16 probs ------------------------
__global__ void __launch_bounds__(256) softmax_rows() {
    const int i = blockIdx.x, b = blockIdx.y;
    const float* p = g_w + ((size_t)b * HW + i) * HW;
    __nv_bfloat16* q = g_p + ((size_t)b * HW + i) * HW;
    const int tid = threadIdx.x;
    __shared__ float red[32];

    float vals[16];
    float mx = -INFINITY;
    #pragma unroll
    for (int t = 0; t < 16; t++) { vals[t] = p[t * 256 + tid]; mx = fmaxf(mx, vals[t]); }
    #pragma unroll
    for (int o = 16; o; o >>= 1) mx = fmaxf(mx, __shfl_xor_sync(0xffffffffu, mx, o));
    if ((tid & 31) == 0) red[tid >> 5] = mx;
    __syncthreads();
    mx = red[0];
    #pragma unroll
    for (int w = 1; w < 8; w++) mx = fmaxf(mx, red[w]);
    __syncthreads();

    float s = 0.f;
    #pragma unroll
    for (int t = 0; t < 16; t++) { vals[t] = __expf(vals[t] - mx); s += vals[t]; }
    #pragma unroll
    for (int o = 16; o; o >>= 1) s += __shfl_xor_sync(0xffffffffu, s, o);
    if ((tid & 31) == 0) red[tid >> 5] = s;
    __syncthreads();
    s = 0.f;
    #pragma unroll
    for (int w = 0; w < 8; w++) s += red[w];
    float inv = 1.0f / s;
    #pragma unroll
    for (int t = 0; t < 16; t++) q[t * 256 + tid] = __float2bfloat16_rn(vals[t] * inv);
}

// ---------------- launch --------------------------------------------------------
extern "C" void kernel_launch(void* const* d_in, const int* in_sizes, int n_in,
                              void* d_out, int out_size) {
    const float* x  = (const float*)d_in[0];
    const float* gs = (const float*)d_in[1];
    const float* gb = (const float*)d_in[2];
    const float* wq = (const float*)d_in[3];
    const float* bq = (const float*)d_in[4];
    const float* wk = (const float*)d_in[5];
    const float* bk = (const float*)d_in[6];
    const float* wv = (const float*)d_in[7];
    const float* bv = (const float*)d_in[8];
    const float* wp = (const float*)d_in[9];
    const float* bp = (const float*)d_in[10];
    float* out = (float*)d_out;

    float *p_of, *p_w, *p_at;
    __nv_bfloat16 *p_qT, *p_kT, *p_v16, *p_p;
    cudaGetSymbolAddress((void**)&p_of,  g_of);
    cudaGetSymbolAddress((void**)&p_qT,  g_qT);
    cudaGetSymbolAddress((void**)&p_kT,  g_kT);
    cudaGetSymbolAddress((void**)&p_v16, g_v16);
    cudaGetSymbolAddress((void**)&p_w,   g_w);
    cudaGetSymbolAddress((void**)&p_p,   g_p);
    cudaGetSymbolAddress((void**)&p_at,  g_at);

    const long long sAct = (long long)CH * HW;
    const long long sW   = (long long)HW * HW;

    // 1) GroupNorm
    gn_stats<<<BATCH * NGROUP, 256>>>(x);
    gn_apply<<<(BATCH * CH * HW / 4 + 255) / 256, 256>>>(x, gs, gb);

    // 2) Q/K/V projections (fp32 SIMT), epilogues emit bf16 in mma-friendly layouts
    dim3 gQKV(HW / 128, CH / 128, BATCH);
    gemm128<true, false, 2><<<gQKV, 256>>>(wq, p_of, p_qT,  CH, HW, CH, 0, sAct, sAct, bq, 1.0f, nullptr);
    gemm128<true, false, 2><<<gQKV, 256>>>(wk, p_of, p_kT,  CH, HW, CH, 0, sAct, sAct, bk, 1.0f, nullptr);
    gemm128<true, false, 1><<<gQKV, 256>>>(wv, p_of, p_v16, CH, HW, CH, 0, sAct, sAct, bv, 1.0f, nullptr);

    // 3) scores (tensor cores): w[i,j] = (1/16) * sum_c Q[i,c] * K[j,c]
    dim3 gS(HW / 128, HW / 128, BATCH);
    mma_gemm<<<gS, 256>>>(p_qT, p_kT, p_w, HW, HW, CH,
                          (long long)HW * CH, (long long)HW * CH, sW, 0.0625f);

    // 4) softmax over j -> bf16 probs
    softmax_rows<<<dim3(HW, BATCH), 256>>>();

    // 5) attn (tensor cores): at[c,i] = sum_j V[c,j] * P[i,j]
    dim3 gA(HW / 128, CH / 128, BATCH);
    mma_gemm<<<gA, 256>>>(p_v16, p_p, p_at, CH, HW, HW,
                          sAct, sW, sAct, 1.0f);

    // 6) proj + bias + residual -> d_out (fp32 SIMT)
    gemm128<true, false, 0><<<gQKV, 256>>>(wp, p_at, out, CH, HW, CH, 0, sAct, sAct, bp, 1.0f, x);
}

// round 3
// speedup vs baseline: 5.8417x; 1.5520x over previous
#include <cuda_runtime.h>
#include <cuda_bf16.h>
#include <math.h>

#define BATCH  4
#define CH     256
#define NGROUP 32
#define HW     4096
#define GEPS   1e-6f

typedef __nv_bfloat16 bf16;

// ---------------- scratch (device globals; no allocation allowed) -------------
__device__ bf16  g_ofT[(size_t)BATCH * HW * CH];   // GN output, transposed [b][i][c]
__device__ bf16  g_q  [(size_t)BATCH * HW * CH];   // Q  [b][i][c]
__device__ bf16  g_k  [(size_t)BATCH * HW * CH];   // K  [b][j][c]
__device__ bf16  g_v  [(size_t)BATCH * CH * HW];   // V  [b][c][j]
__device__ bf16  g_atT[(size_t)BATCH * HW * CH];   // attn out transposed [b][i][c]
__device__ float g_w  [(size_t)BATCH * HW * HW];   // scores fp32 (268 MB)
__device__ bf16  g_p  [(size_t)BATCH * HW * HW];   // probs bf16 (134 MB)
__device__ bf16  g_w16[4 * CH * CH];               // bf16 weights: wq|wk|wv|wp
__device__ float g_mean[BATCH * NGROUP];
__device__ float g_rstd[BATCH * NGROUP];

// ---------------- GroupNorm: stats --------------------------------------------
__global__ void __launch_bounds__(256) gn_stats(const float* __restrict__ x) {
    const int bg = blockIdx.x;
    const float* p = x + (size_t)bg * (CH / NGROUP) * HW;
    const int tid = threadIdx.x;

    float s = 0.f, s2 = 0.f;
    const int n4 = (CH / NGROUP) * HW / 4;
    for (int i = tid; i < n4; i += 256) {
        float4 v = ((const float4*)p)[i];
        s  += v.x + v.y + v.z + v.w;
        s2 += v.x * v.x + v.y * v.y + v.z * v.z + v.w * v.w;
    }
    __shared__ float red[64];
    #pragma unroll
    for (int o = 16; o; o >>= 1) {
        s  += __shfl_xor_sync(0xffffffffu, s,  o);
        s2 += __shfl_xor_sync(0xffffffffu, s2, o);
    }
    if ((tid & 31) == 0) { red[tid >> 5] = s; red[32 + (tid >> 5)] = s2; }
    __syncthreads();
    if (tid == 0) {
        float ts = 0.f, ts2 = 0.f;
        #pragma unroll
        for (int w = 0; w < 8; w++) { ts += red[w]; ts2 += red[32 + w]; }
        const float inv_n = 1.0f / ((CH / NGROUP) * HW);
        float mean = ts * inv_n;
        float var  = ts2 * inv_n - mean * mean;
        g_mean[bg] = mean;
        g_rstd[bg] = rsqrtf(var + GEPS);
    }
}

// ---------------- GroupNorm apply + transpose -> bf16 OF^T [b][i][c] -----------
// 32x32 tiles, block (32,8). Read x[b][c][i] coalesced, write [i][c] as bf162.
__global__ void __launch_bounds__(256) gn_apply_t(const float* __restrict__ x,
                                                  const float* __restrict__ gs,
                                                  const float* __restrict__ gb) {
    __shared__ float tile[32][33];
    const int i0 = blockIdx.x * 32, c0 = blockIdx.y * 32, b = blockIdx.z;
    const int tx = threadIdx.x, ty = threadIdx.y;

    #pragma unroll
    for (int dy = 0; dy < 4; dy++) {
        int c = c0 + ty + dy * 8;
        int bg = b * NGROUP + (c >> 3);          // 8 channels per group
        float r = g_rstd[bg];
        float a = gs[c] * r;
        float t = gb[c] - g_mean[bg] * a;
        float v = x[((size_t)b * CH + c) * HW + i0 + tx];
        tile[ty + dy * 8][tx] = v * a + t;
    }
    __syncthreads();

    const int tid = ty * 32 + tx;
    #pragma unroll
    for (int h = 0; h < 2; h++) {
        int p = tid + h * 256;                   // 512 bf162 pairs per tile
        int il = p >> 4, cl = (p & 15) * 2;
        __nv_bfloat162 o;
        o.x = __float2bfloat16_rn(tile[cl][il]);
        o.y = __float2bfloat16_rn(tile[cl + 1][il]);
        *(__nv_bfloat162*)(&g_ofT[((size_t)b * HW + i0 + il) * CH + c0 + cl]) = o;
    }
}

// ---------------- weights -> bf16 ----------------------------------------------
__global__ void __launch_bounds__(256) conv_w(const float* __restrict__ wq,
                                              const float* __restrict__ wk,
                                              const float* __restrict__ wv,
                                              const float* __restrict__ wp) {
    int i = blockIdx.x * 256 + threadIdx.x;
    if (i >= CH * CH) return;
    g_w16[0 * CH * CH + i] = __float2bfloat16_rn(wq[i]);
    g_w16[1 * CH * CH + i] = __float2bfloat16_rn(wk[i]);
    g_w16[2 * CH * CH + i] = __float2bfloat16_rn(wv[i]);
    g_w16[3 * CH * CH + i] = __float2bfloat16_rn(wp[i]);
}

// ---------------- bf16 tensor-core GEMM ----------------------------------------
// D[m][n] = scale * sum_k A[m][k]*B[n][k] (+ epilogue)
// A: [M][K] bf16 k-contig, B: [N][K] bf16 k-contig.
// EPI 0: fp32 out, *scale.           EPI 1: bf16 out + bias[n].
// EPI 2: bf16 out + bias[m].         EPI 3: bf16 out.
// EPI 4: fp32 out + bias[m] + resid[m][n].
// CTA 128x128, BK=32, 8 warps (2m x 4n), mma m16n8k16, cp.async double-buffered.

__device__ __forceinline__ unsigned swz(int m, int c) {  // 16B-chunk index in [128][32]bf16 tile
    return (unsigned)((m << 2) + (c ^ ((m >> 1) & 3)));
}

#define CP16(dst_u32, src_ptr) \
    asm volatile("cp.async.cg.shared.global [%0], [%1], 16;\n" :: "r"(dst_u32), "l"(src_ptr))
#define LDMX4(r0, r1, r2, r3, addr) \
    asm volatile("ldmatrix.sync.aligned.m8n8.x4.shared.b16 {%0,%1,%2,%3}, [%4];\n" \
                 : "=r"(r0), "=r"(r1), "=r"(r2), "=r"(r3) : "r"(addr))
#define MMA16816(c0, c1, c2, c3, a0, a1, a2, a3, b0, b1) \
    asm volatile("mma.sync.aligned.m16n8k16.row.col.f32.bf16.bf16.f32 " \
                 "{%0,%1,%2,%3}, {%4,%5,%6,%7}, {%8,%9}, {%0,%1,%2,%3};\n" \
                 : "+f"(c0), "+f"(c1), "+f"(c2), "+f"(c3) \
                 : "r"(a0), "r"(a1), "r"(a2), "r"(a3), "r"(b0), "r"(b1))

template<int EPI>
__global__ void __launch_bounds__(256) mma_gemm(
    const bf16* __restrict__ A, const bf16* __restrict__ B,
    void* __restrict__ Dv, int M, int N, int K,
    long long sA, long long sB, long long sD, float scale,
    const float* __restrict__ bias, const float* __restrict__ resid)
{
    __shared__ __align__(16) unsigned char sm[2 * 16384];   // [stage][A 8KB | B 8KB]
    const int bz = blockIdx.z;
    A += (size_t)bz * sA;
    B += (size_t)bz * sB;
    const int m0 = blockIdx.y * 128, n0 = blockIdx.x * 128;
    const int tid = threadIdx.x, lane = tid & 31, warp = tid >> 5;
    const int wm = warp >> 2, wn = warp & 3;

    const unsigned smbase = (unsigned)__cvta_generic_to_shared(sm);

    const int lm = tid >> 2, lc = tid & 3;
    const bf16* gA0 = A + (size_t)(m0 + lm)      * K + lc * 8;
    const bf16* gA1 = A + (size_t)(m0 + lm + 64) * K + lc * 8;
    const bf16* gB0 = B + (size_t)(n0 + lm)      * K + lc * 8;
    const bf16* gB1 = B + (size_t)(n0 + lm + 64) * K + lc * 8;
    const unsigned dA0 = swz(lm, lc) * 16u;
    const unsigned dA1 = swz(lm + 64, lc) * 16u;
    const unsigned dB0 = 8192u + swz(lm, lc) * 16u;
    const unsigned dB1 = 8192u + swz(lm + 64, lc) * 16u;

    unsigned aOff[4], bOff[2];
    {
        int r = wm * 64 + (lane & 15);
        int c0 = lane >> 4;
        #pragma unroll
        for (int mt = 0; mt < 4; mt++) aOff[mt] = swz(r + mt * 16, c0) * 16u;
    }
    {
        int r = wn * 32 + ((lane >> 4) << 3) + (lane & 7);
        int c0 = (lane >> 3) & 1;
        #pragma unroll
        for (int p = 0; p < 2; p++) bOff[p] = 8192u + swz(r + p * 16, c0) * 16u;
    }

    float acc[4][4][4];
    #pragma unroll
    for (int i = 0; i < 4; i++)
        #pragma unroll
        for (int j = 0; j < 4; j++)
            #pragma unroll
            for (int r = 0; r < 4; r++) acc[i][j][r] = 0.f;

    const int iters = K >> 5;

    {
        unsigned s = smbase;
        CP16(s + dA0, gA0); CP16(s + dA1, gA1);
        CP16(s + dB0, gB0); CP16(s + dB1, gB1);
        asm volatile("cp.async.commit_group;\n");
    }

    for (int it = 0; it < iters; ++it) {
        const int cur = it & 1;
        if (it + 1 < iters) {
            unsigned s = smbase + (unsigned)(cur ^ 1) * 16384u;
            int k0 = (it + 1) << 5;
            CP16(s + dA0, gA0 + k0); CP16(s + dA1, gA1 + k0);
            CP16(s + dB0, gB0 + k0); CP16(s + dB1, gB1 + k0);
            asm volatile("cp.async.commit_group;\n");
            asm volatile("cp.async.wait_group 1;\n");
        } else {
            asm volatile("cp.async.wait_group 0;\n");
        }
        __syncthreads();

        const unsigned sb = smbase + (unsigned)cur * 16384u;
        #pragma unroll
        for (int ks = 0; ks < 2; ++ks) {
            const unsigned kx = (unsigned)ks * 32u;
            unsigned a[4][4], b[2][4];
            #pragma unroll
            for (int mt = 0; mt < 4; mt++)
                LDMX4(a[mt][0], a[mt][1], a[mt][2], a[mt][3], sb + (aOff[mt] ^ kx));
            #pragma unroll
            for (int p = 0; p < 2; p++)
                LDMX4(b[p][0], b[p][1], b[p][2], b[p][3], sb + (bOff[p] ^ kx));

            #pragma unroll
            for (int mt = 0; mt < 4; mt++) {
                #pragma unroll
                for (int nt = 0; nt < 4; nt++) {
                    const int p = nt >> 1, h = (nt & 1) << 1;
                    MMA16816(acc[mt][nt][0], acc[mt][nt][1], acc[mt][nt][2], acc[mt][nt][3],
                             a[mt][0], a[mt][1], a[mt][2], a[mt][3],
                             b[p][h + 0], b[p][h + 1]);
                }
            }
        }
        __syncthreads();
    }

    // epilogue: c0 @(r,cc) c1 @(r,cc+1) c2 @(r+8,cc) c3 @(r+8,cc+1)
    const int row = m0 + wm * 64 + (lane >> 2);
    const int col = n0 + wn * 32 + (lane & 3) * 2;

    if (EPI == 0 || EPI == 4) {
        float* D = (float*)Dv + (size_t)bz * sD;
        const float* R = (EPI == 4) ? resid + (size_t)bz * sD : nullptr;
        #pragma unroll
        for (int mt = 0; mt < 4; mt++) {
            #pragma unroll
            for (int nt = 0; nt < 4; nt++) {
                int r = row + mt * 16, cc = col + nt * 8;
                float b0 = 0.f, b1 = 0.f;
                if (EPI == 4) { b0 = bias[r]; b1 = bias[r + 8]; }
                float2 v0 = { acc[mt][nt][0] * scale + b0, acc[mt][nt][1] * scale + b0 };
                float2 v1 = { acc[mt][nt][2] * scale + b1, acc[mt][nt][3] * scale + b1 };
                if (EPI == 4) {
                    float2 r0 = *(const float2*)(&R[(size_t)r * N + cc]);
                    float2 r1 = *(const float2*)(&R[(size_t)(r + 8) * N + cc]);
                    v0.x += r0.x; v0.y += r0.y; v1.x += r1.x; v1.y += r1.y;
                }
                *(float2*)(&D[(size_t)r * N + cc])       = v0;
                *(float2*)(&D[(size_t)(r + 8) * N + cc]) = v1;
            }
        }
    } else {
        bf16* D = (bf16*)Dv + (size_t)bz * sD;
        #pragma unroll
        for (int mt = 0; mt < 4; mt++) {
            #pragma unroll
            for (int nt = 0; nt < 4; nt++) {
                int r = row + mt * 16, cc = col + nt * 8;
                float bn0 = 0.f, bn1 = 0.f, bm0 = 0.f, bm1 = 0.f;
                if (EPI == 1) { bn0 = bias[cc]; bn1 = bias[cc + 1]; }
                if (EPI == 2) { bm0 = bias[r];  bm1 = bias[r + 8]; }
                __nv_bfloat162 o0, o1;
                o0.x = __float2bfloat16_rn(acc[mt][nt][0] + bn0 + bm0);
                o0.y = __float2bfloat16_rn(acc[mt][nt][1] + bn1 + bm0);
                o1.x = __float2bfloat16_rn(acc[mt][nt][2] + bn0 + bm1);
                o1.y = __float2bfloat16_rn(acc[mt][nt][3] + bn1 + bm1);
                *(__nv_bfloat162*)(&D[(size_t)r * N + cc])       = o0;
                *(__nv_bfloat162*)(&D[(size_t)(r + 8) * N + cc]) = o1;
            }
        }
    }
}

// ---------------- row softmax: fp32 scores -> bf16 probs ------------------------
__global__ void __launch_bounds__(256) softmax_rows() {
    const int i = blockIdx.x, b = blockIdx.y;
    const float* p = g_w + ((size_t)b * HW + i) * HW;
    bf16* q = g_p + ((size_t)b * HW + i) * HW;
    const int tid = threadIdx.x;
    __shared__ float red[32];

    float vals[16];
    float mx = -INFINITY;
    #pragma unroll
    for (int t = 0; t < 16; t++) { vals[t] = p[t * 256 + tid]; mx = fmaxf(mx, vals[t]); }
    #pragma unroll
    for (int o = 16; o; o >>= 1) mx = fmaxf(mx, __shfl_xor_sync(0xffffffffu, mx, o));
    if ((tid & 31) == 0) red[tid >> 5] = mx;
    __syncthreads();
    mx = red[0];
    #pragma unroll
    for (int w = 1; w < 8; w++) mx = fmaxf(mx, red[w]);
    __syncthreads();

    float s = 0.f;
    #pragma unroll
    for (int t = 0; t < 16; t++) { vals[t] = __expf(vals[t] - mx); s += vals[t]; }
    #pragma unroll
    for (int o = 16; o; o >>= 1) s += __shfl_xor_sync(0xffffffffu, s, o);
    if ((tid & 31) == 0) red[tid >> 5] = s;
    __syncthreads();
    s = 0.f;
    #pragma unroll
    for (int w = 0; w < 8; w++) s += red[w];
    float inv = 1.0f / s;
    #pragma unroll
    for (int t = 0; t < 16; t++) q[t * 256 + tid] = __float2bfloat16_rn(vals[t] * inv);
}

// ---------------- launch --------------------------------------------------------
extern "C" void kernel_launch(void* const* d_in, const int* in_sizes, int n_in,
                              void* d_out, int out_size) {
    const float* x  = (const float*)d_in[0];
    const float* gs = (const float*)d_in[1];
    const float* gb = (const float*)d_in[2];
    const float* wq = (const float*)d_in[3];
    const float* bq = (const float*)d_in[4];
    const float* wk = (const float*)d_in[5];
    const float* bk = (const float*)d_in[6];
    const float* wv = (const float*)d_in[7];
    const float* bv = (const float*)d_in[8];
    const float* wp = (const float*)d_in[9];
    const float* bp = (const float*)d_in[10];
    float* out = (float*)d_out;

    bf16 *p_ofT, *p_q, *p_k, *p_v, *p_atT, *p_p, *p_w16;
    float *p_w;
    cudaGetSymbolAddress((void**)&p_ofT, g_ofT);
    cudaGetSymbolAddress((void**)&p_q,   g_q);
    cudaGetSymbolAddress((void**)&p_k,   g_k);
    cudaGetSymbolAddress((void**)&p_v,   g_v);
    cudaGetSymbolAddress((void**)&p_atT, g_atT);
    cudaGetSymbolAddress((void**)&p_p,   g_p);
    cudaGetSymbolAddress((void**)&p_w16, g_w16);
    cudaGetSymbolAddress((void**)&p_w,   g_w);

    const long long sIC = (long long)HW * CH;   // [i][c] per-batch stride
    const long long sCI = (long long)CH * HW;   // [c][i] per-batch stride
    const long long sW  = (long long)HW * HW;

    // 1) GroupNorm (stats + apply/transpose) and weight conversion
    gn_stats<<<BATCH * NGROUP, 256>>>(x);
    conv_w<<<CH * CH / 256, 256>>>(wq, wk, wv, wp);
    gn_apply_t<<<dim3(HW / 32, CH / 32, BATCH), dim3(32, 8)>>>(x, gs, gb);

    // 2) Q/K: [i][c] = OF^T x W^T + bias[n]
    dim3 gQK(CH / 128, HW / 128, BATCH);
    mma_gemm<1><<<gQK, 256>>>(p_ofT, p_w16 + 0 * CH * CH, p_q, HW, CH, CH, sIC, 0, sIC, 1.0f, bq, nullptr);
    mma_gemm<1><<<gQK, 256>>>(p_ofT, p_w16 + 1 * CH * CH, p_k, HW, CH, CH, sIC, 0, sIC, 1.0f, bk, nullptr);
    // V: [c][j] = W x OF + bias[m]
    dim3 gV(HW / 128, CH / 128, BATCH);
    mma_gemm<2><<<gV, 256>>>(p_w16 + 2 * CH * CH, p_ofT, p_v, CH, HW, CH, 0, sIC, sCI, 1.0f, bv, nullptr);

    // 3) scores: w[i,j] = (1/16) * sum_c Q[i,c] K[j,c]
    dim3 gS(HW / 128, HW / 128, BATCH);
    mma_gemm<0><<<gS, 256>>>(p_q, p_k, p_w, HW, HW, CH, sIC, sIC, sW, 0.0625f, nullptr, nullptr);

    // 4) softmax over j -> bf16 probs
    softmax_rows<<<dim3(HW, BATCH), 256>>>();

    // 5) attn (transposed): atT[i][c] = sum_j P[i,j] V[c,j]
    dim3 gA(CH / 128, HW / 128, BATCH);
    mma_gemm<3><<<gA, 256>>>(p_p, p_v, p_atT, HW, CH, HW, sW, sCI, sIC, 1.0f, nullptr, nullptr);

    // 6) proj + bias + residual -> d_out: out[c][i] = sum_cm wp[c,cm] atT[i,cm] + bp[c] + x[c][i]
    dim3 gP(HW / 128, CH / 128, BATCH);
    mma_gemm<4><<<gP, 256>>>(p_w16 + 3 * CH * CH, p_atT, out, CH, HW, CH, 0, sIC, sCI, 1.0f, bp, x);
}

// round 5
// speedup vs baseline: 6.6606x; 1.1402x over previous
#include <cuda_runtime.h>
#include <cuda_bf16.h>
#include <math.h>
#include <stdint.h>

#define BATCH  4
#define CH     256
#define NGROUP 32
#define HW     4096
#define GEPS   1e-6f
#define STAGES 4

typedef __nv_bfloat16 bf16;

// ---------------- scratch (device globals; no allocation allowed) -------------
__device__ bf16  g_ofT[(size_t)BATCH * HW * CH];   // GN output, transposed [b][i][c]
__device__ bf16  g_q  [(size_t)BATCH * HW * CH];   // Q  [b][i][c]
__device__ bf16  g_k  [(size_t)BATCH * HW * CH];   // K  [b][j][c]
__device__ bf16  g_v  [(size_t)BATCH * CH * HW];   // V  [b][c][j]
__device__ bf16  g_atT[(size_t)BATCH * HW * CH];   // attn out transposed [b][i][c]
__device__ bf16  g_s  [(size_t)BATCH * HW * HW];   // scores -> probs bf16 in place (134MB)
__device__ bf16  g_w16[4 * CH * CH];               // bf16 weights: wq|wk|wv|wp
__device__ float g_mean[BATCH * NGROUP];
__device__ float g_rstd[BATCH * NGROUP];

// ---------------- GroupNorm: stats --------------------------------------------
__global__ void __launch_bounds__(256) gn_stats(const float* __restrict__ x) {
    const int bg = blockIdx.x;
    const float* p = x + (size_t)bg * (CH / NGROUP) * HW;
    const int tid = threadIdx.x;

    float s = 0.f, s2 = 0.f;
    const int n4 = (CH / NGROUP) * HW / 4;
    for (int i = tid; i < n4; i += 256) {
        float4 v = ((const float4*)p)[i];
        s  += v.x + v.y + v.z + v.w;
        s2 += v.x * v.x + v.y * v.y + v.z * v.z + v.w * v.w;
    }
    __shared__ float red[64];
    #pragma unroll
    for (int o = 16; o; o >>= 1) {
        s  += __shfl_xor_sync(0xffffffffu, s,  o);
        s2 += __shfl_xor_sync(0xffffffffu, s2, o);
    }
    if ((tid & 31) == 0) { red[tid >> 5] = s; red[32 + (tid >> 5)] = s2; }
    __syncthreads();
    if (tid == 0) {
        float ts = 0.f, ts2 = 0.f;
        #pragma unroll
        for (int w = 0; w < 8; w++) { ts += red[w]; ts2 += red[32 + w]; }
        const float inv_n = 1.0f / ((CH / NGROUP) * HW);
        float mean = ts * inv_n;
        float var  = ts2 * inv_n - mean * mean;
        g_mean[bg] = mean;
        g_rstd[bg] = rsqrtf(var + GEPS);
    }
}

// ---------------- GroupNorm apply + transpose -> bf16 OF^T [b][i][c] -----------
__global__ void __launch_bounds__(256) gn_apply_t(const float* __restrict__ x,
                                                  const float* __restrict__ gs,
                                                  const float* __restrict__ gb) {
    __shared__ float tile[32][33];
    const int i0 = blockIdx.x * 32, c0 = blockIdx.y * 32, b = blockIdx.z;
    const int tx = threadIdx.x, ty = threadIdx.y;

    #pragma unroll
    for (int dy = 0; dy < 4; dy++) {
        int c = c0 + ty + dy * 8;
        int bg = b * NGROUP + (c >> 3);
        float r = g_rstd[bg];
        float a = gs[c] * r;
        float t = gb[c] - g_mean[bg] * a;
        float v = x[((size_t)b * CH + c) * HW + i0 + tx];
        tile[ty + dy * 8][tx] = v * a + t;
    }
    __syncthreads();

    const int tid = ty * 32 + tx;
    #pragma unroll
    for (int h = 0; h < 2; h++) {
        int p = tid + h * 256;
        int il = p >> 4, cl = (p & 15) * 2;
        __nv_bfloat162 o;
        o.x = __float2bfloat16_rn(tile[cl][il]);
        o.y = __float2bfloat16_rn(tile[cl + 1][il]);
        *(__nv_bfloat162*)(&g_ofT[((size_t)b * HW + i0 + il) * CH + c0 + cl]) = o;
    }
}

// ---------------- weights -> bf16 ----------------------------------------------
__global__ void __launch_bounds__(256) conv_w(const float* __restrict__ wq,
                                              const float* __restrict__ wk,
                                              const float* __restrict__ wv,
                                              const float* __restrict__ wp) {
    int i = blockIdx.x * 256 + threadIdx.x;
    if (i >= CH * CH) return;
    g_w16[0 * CH * CH + i] = __float2bfloat16_rn(wq[i]);
    g_w16[1 * CH * CH + i] = __float2bfloat16_rn(wk[i]);
    g_w16[2 * CH * CH + i] = __float2bfloat16_rn(wv[i]);
    g_w16[3 * CH * CH + i] = __float2bfloat16_rn(wp[i]);
}

// ---------------- bf16 tensor-core GEMM (mma.sync HMMA) -------------------------
// D[m][n] = scale * sum_k A[m][k]*B[n][k] (+ epilogue)
// A: [M][K] bf16 k-contig, B: [N][K] bf16 k-contig.
// EPI 1: bf16 out*scale + bias[n].  EPI 2: bf16 out*scale + bias[m].
// EPI 3: bf16 out*scale.            EPI 4: fp32 out + bias[m] + resid[m][n].
// CTA 128x128, BK=32, 8 warps (2m x 4n), mma m16n8k16, 4-stage cp.async, 1 sync/iter.

__device__ __forceinline__ unsigned swz(int m, int c) {  // 16B-chunk index in [128][32]bf16 tile
    return (unsigned)((m << 2) + (c ^ ((m >> 1) & 3)));
}

#define CP16(dst_u32, src_ptr) \
    asm volatile("cp.async.cg.shared.global [%0], [%1], 16;\n" :: "r"(dst_u32), "l"(src_ptr))
#define LDMX4(r0, r1, r2, r3, addr) \
    asm volatile("ldmatrix.sync.aligned.m8n8.x4.shared.b16 {%0,%1,%2,%3}, [%4];\n" \
                 : "=r"(r0), "=r"(r1), "=r"(r2), "=r"(r3) : "r"(addr))
#define MMA16816(c0, c1, c2, c3, a0, a1, a2, a3, b0, b1) \
    asm volatile("mma.sync.aligned.m16n8k16.row.col.f32.bf16.bf16.f32 " \
                 "{%0,%1,%2,%3}, {%4,%5,%6,%7}, {%8,%9}, {%0,%1,%2,%3};\n" \
                 : "+f"(c0), "+f"(c1), "+f"(c2), "+f"(c3) \
                 : "r"(a0), "r"(a1), "r"(a2), "r"(a3), "r"(b0), "r"(b1))

#define GEMM_SMEM_BYTES (STAGES * 16384)

template<int EPI>
__global__ void __launch_bounds__(256) mma_gemm(
    const bf16* __restrict__ A, const bf16* __restrict__ B,
    void* __restrict__ Dv, int M, int N, int K,
    long long sA, long long sB, long long sD, float scale,
    const float* __restrict__ bias, const float* __restrict__ resid)
{
    extern __shared__ __align__(16) unsigned char sm[];   // STAGES x [A 8KB | B 8KB]
    const int bz = blockIdx.z;
    A += (size_t)bz * sA;
    B += (size_t)bz * sB;
    const int m0 = blockIdx.y * 128, n0 = blockIdx.x * 128;
    const int tid = threadIdx.x, lane = tid & 31, warp = tid >> 5;
    const int wm = warp >> 2, wn = warp & 3;

    const unsigned smbase = (unsigned)__cvta_generic_to_shared(sm);

    const int lm = tid >> 2, lc = tid & 3;
    const bf16* gA0 = A + (size_t)(m0 + lm)      * K + lc * 8;
    const bf16* gA1 = A + (size_t)(m0 + lm + 64) * K + lc * 8;
    const bf16* gB0 = B + (size_t)(n0 + lm)      * K + lc * 8;
    const bf16* gB1 = B + (size_t)(n0 + lm + 64) * K + lc * 8;
    const unsigned dA0 = swz(lm, lc) * 16u;
    const unsigned dA1 = swz(lm + 64, lc) * 16u;
    const unsigned dB0 = 8192u + swz(lm, lc) * 16u;
    const unsigned dB1 = 8192u + swz(lm + 64, lc) * 16u;

    unsigned aOff[4], bOff[2];
    {
        int r = wm * 64 + (lane & 15);
        int c0 = lane >> 4;
        #pragma unroll
        for (int mt = 0; mt < 4; mt++) aOff[mt] = swz(r + mt * 16, c0) * 16u;
    }
    {
        int r = wn * 32 + ((lane >> 4) << 3) + (lane & 7);
        int c0 = (lane >> 3) & 1;
        #pragma unroll
        for (int p = 0; p < 2; p++) bOff[p] = 8192u + swz(r + p * 16, c0) * 16u;
    }

    float acc[4][4][4];
    #pragma unroll
    for (int i = 0; i < 4; i++)
        #pragma unroll
        for (int j = 0; j < 4; j++)
            #pragma unroll
            for (int r = 0; r < 4; r++) acc[i][j][r] = 0.f;

    const int iters = K >> 5;           // K >= 256 -> iters >= 8 > STAGES-1

    // prologue: fill stages 0..STAGES-2
    #pragma unroll
    for (int s = 0; s < STAGES - 1; ++s) {
        unsigned st = smbase + (unsigned)s * 16384u;
        int k0 = s << 5;
        CP16(st + dA0, gA0 + k0); CP16(st + dA1, gA1 + k0);
        CP16(st + dB0, gB0 + k0); CP16(st + dB1, gB1 + k0);
        asm volatile("cp.async.commit_group;\n");
    }

    for (int it = 0; it < iters; ++it) {
        asm volatile("cp.async.wait_group %0;\n" :: "n"(STAGES - 2));
        __syncthreads();

        // prefetch stage it+STAGES-1 into buffer (it-1)%STAGES (freed by the sync above)
        {
            int pf = it + STAGES - 1;
            if (pf < iters) {
                unsigned st = smbase + (unsigned)(pf & (STAGES - 1)) * 16384u;
                int k0 = pf << 5;
                CP16(st + dA0, gA0 + k0); CP16(st + dA1, gA1 + k0);
                CP16(st + dB0, gB0 + k0); CP16(st + dB1, gB1 + k0);
            }
            asm volatile("cp.async.commit_group;\n");   // empty group at tail keeps count uniform
        }

        const unsigned sb = smbase + (unsigned)(it & (STAGES - 1)) * 16384u;
        #pragma unroll
        for (int ks = 0; ks < 2; ++ks) {
            const unsigned kx = (unsigned)ks * 32u;
            unsigned a[4][4], b[2][4];
            #pragma unroll
            for (int mt = 0; mt < 4; mt++)
                LDMX4(a[mt][0], a[mt][1], a[mt][2], a[mt][3], sb + (aOff[mt] ^ kx));
            #pragma unroll
            for (int p = 0; p < 2; p++)
                LDMX4(b[p][0], b[p][1], b[p][2], b[p][3], sb + (bOff[p] ^ kx));

            #pragma unroll
            for (int mt = 0; mt < 4; mt++) {
                #pragma unroll
                for (int nt = 0; nt < 4; nt++) {
                    const int p = nt >> 1, h = (nt & 1) << 1;
                    MMA16816(acc[mt][nt][0], acc[mt][nt][1], acc[mt][nt][2], acc[mt][nt][3],
                             a[mt][0], a[mt][1], a[mt][2], a[mt][3],
                             b[p][h + 0], b[p][h + 1]);
                }
            }
        }
    }

    // epilogue: c0 @(r,cc) c1 @(r,cc+1) c2 @(r+8,cc) c3 @(r+8,cc+1)
    const int row = m0 + wm * 64 + (lane >> 2);
    const int col = n0 + wn * 32 + (lane & 3) * 2;

    if (EPI == 4) {
        float* D = (float*)Dv + (size_t)bz * sD;
        const float* R = resid + (size_t)bz * sD;
        #pragma unroll
        for (int mt = 0; mt < 4; mt++) {
            #pragma unroll
            for (int nt = 0; nt < 4; nt++) {
                int r = row + mt * 16, cc = col + nt * 8;
                float b0 = bias[r], b1 = bias[r + 8];
                float2 v0 = { acc[mt][nt][0] + b0, acc[mt][nt][1] + b0 };
                float2 v1 = { acc[mt][nt][2] + b1, acc[mt][nt][3] + b1 };
                float2 r0 = *(const float2*)(&R[(size_t)r * N + cc]);
                float2 r1 = *(const float2*)(&R[(size_t)(r + 8) * N + cc]);
                v0.x += r0.x; v0.y += r0.y; v1.x += r1.x; v1.y += r1.y;
                *(float2*)(&D[(size_t)r * N + cc])       = v0;
                *(float2*)(&D[(size_t)(r + 8) * N + cc]) = v1;
            }
        }
    } else {
        bf16* D = (bf16*)Dv + (size_t)bz * sD;
        #pragma unroll
        for (int mt = 0; mt < 4; mt++) {
            #pragma unroll
            for (int nt = 0; nt < 4; nt++) {
                int r = row + mt * 16, cc = col + nt * 8;
                float bn0 = 0.f, bn1 = 0.f, bm0 = 0.f, bm1 = 0.f;
                if (EPI == 1) { bn0 = bias[cc]; bn1 = bias[cc + 1]; }
                if (EPI == 2) { bm0 = bias[r];  bm1 = bias[r + 8]; }
                __nv_bfloat162 o0, o1;
                o0.x = __float2bfloat16_rn(acc[mt][nt][0] * scale + bn0 + bm0);
                o0.y = __float2bfloat16_rn(acc[mt][nt][1] * scale + bn1 + bm0);
                o1.x = __float2bfloat16_rn(acc[mt][nt][2] * scale + bn0 + bm1);
                o1.y = __float2bfloat16_rn(acc[mt][nt][3] * scale + bn1 + bm1);
                *(__nv_bfloat162*)(&D[(size_t)r * N + cc])       = o0;
                *(__nv_bfloat162*)(&D[(size_t)(r + 8) * N + cc]) = o1;
            }
        }
    }
}

// ---------------- row softmax, bf16 in place -------------------------------------
__global__ void __launch_bounds__(256) softmax_rows(bf16* __restrict__ S) {
    const int i = blockIdx.x, b = blockIdx.y;
    bf16* p = S + ((size_t)b * HW + i) * HW;
    const int tid = threadIdx.x;
    __shared__ float red[32];

    bf16 v[16];
    *(uint4*)(v)     = ((const uint4*)p)[tid];
    *(uint4*)(v + 8) = ((const uint4*)p)[tid + 256];
    float f[16];
    float mx = -INFINITY;
    #pragma unroll
    for (int t = 0; t < 16; t++) { f[t] = __bfloat162float(v[t]); mx = fmaxf(mx, f[t]); }
    #pragma unroll
    for (int o = 16; o; o >>= 1) mx = fmaxf(mx, __shfl_xor_sync(0xffffffffu, mx, o));
    if ((tid & 31) == 0) red[tid >> 5] = mx;
    __syncthreads();
    mx = red[0];
    #pragma unroll
    for (int w = 1; w < 8; w++) mx = fmaxf(mx, red[w]);
    __syncthreads();

    float s = 0.f;
    #pragma unroll
    for (int t = 0; t < 16; t++) { f[t] = __expf(f[t] - mx); s += f[t]; }
    #pragma unroll
    for (int o = 16; o; o >>= 1) s += __shfl_xor_sync(0xffffffffu, s, o);
    if ((tid & 31) == 0) red[tid >> 5] = s;
    __syncthreads();
    s = 0.f;
    #pragma unroll
    for (int w = 0; w < 8; w++) s += red[w];
    const float inv = 1.0f / s;
    #pragma unroll
    for (int t = 0; t < 16; t++) v[t] = __float2bfloat16_rn(f[t] * inv);
    ((uint4*)p)[tid]       = *(uint4*)(v);
    ((uint4*)p)[tid + 256] = *(uint4*)(v + 8);
}

// ---------------- launch --------------------------------------------------------
extern "C" void kernel_launch(void* const* d_in, const int* in_sizes, int n_in,
                              void* d_out, int out_size) {
    const float* x  = (const float*)d_in[0];
    const float* gs = (const float*)d_in[1];
    const float* gb = (const float*)d_in[2];
    const float* wq = (const float*)d_in[3];
    const float* bq = (const float*)d_in[4];
    const float* wk = (const float*)d_in[5];
    const float* bk = (const float*)d_in[6];
    const float* wv = (const float*)d_in[7];
    const float* bv = (const float*)d_in[8];
    const float* wp = (const float*)d_in[9];
    const float* bp = (const float*)d_in[10];
    float* out = (float*)d_out;

    bf16 *p_ofT, *p_q, *p_k, *p_v, *p_atT, *p_s, *p_w16;
    cudaGetSymbolAddress((void**)&p_ofT, g_ofT);
    cudaGetSymbolAddress((void**)&p_q,   g_q);
    cudaGetSymbolAddress((void**)&p_k,   g_k);
    cudaGetSymbolAddress((void**)&p_v,   g_v);
    cudaGetSymbolAddress((void**)&p_atT, g_atT);
    cudaGetSymbolAddress((void**)&p_s,   g_s);
    cudaGetSymbolAddress((void**)&p_w16, g_w16);

    cudaFuncSetAttribute(mma_gemm<1>, cudaFuncAttributeMaxDynamicSharedMemorySize, GEMM_SMEM_BYTES);
    cudaFuncSetAttribute(mma_gemm<2>, cudaFuncAttributeMaxDynamicSharedMemorySize, GEMM_SMEM_BYTES);
    cudaFuncSetAttribute(mma_gemm<3>, cudaFuncAttributeMaxDynamicSharedMemorySize, GEMM_SMEM_BYTES);
    cudaFuncSetAttribute(mma_gemm<4>, cudaFuncAttributeMaxDynamicSharedMemorySize, GEMM_SMEM_BYTES);

    const long long sIC = (long long)HW * CH;   // [i][c] per-batch stride
    const long long sCI = (long long)CH * HW;   // [c][i] per-batch stride
    const long long sW  = (long long)HW * HW;

    // 1) GroupNorm + weight conversion
    gn_stats<<<BATCH * NGROUP, 256>>>(x);
    conv_w<<<CH * CH / 256, 256>>>(wq, wk, wv, wp);
    gn_apply_t<<<dim3(HW / 32, CH / 32, BATCH), dim3(32, 8)>>>(x, gs, gb);

    // 2) Q/K: [i][c_out] = OF^T x W^T + bias[n]
    dim3 gQK(CH / 128, HW / 128, BATCH);
    mma_gemm<1><<<gQK, 256, GEMM_SMEM_BYTES>>>(p_ofT, p_w16 + 0 * CH * CH, p_q, HW, CH, CH, sIC, 0, sIC, 1.0f, bq, nullptr);
    mma_gemm<1><<<gQK, 256, GEMM_SMEM_BYTES>>>(p_ofT, p_w16 + 1 * CH * CH, p_k, HW, CH, CH, sIC, 0, sIC, 1.0f, bk, nullptr);
    // V: [c][j] = W x OF + bias[m]
    dim3 gV(HW / 128, CH / 128, BATCH);
    mma_gemm<2><<<gV, 256, GEMM_SMEM_BYTES>>>(p_w16 + 2 * CH * CH, p_ofT, p_v, CH, HW, CH, 0, sIC, sCI, 1.0f, bv, nullptr);

    // 3) scores (bf16 out): s[i,j] = (1/16) * sum_c Q[i,c] K[j,c]
    dim3 gS(HW / 128, HW / 128, BATCH);
    mma_gemm<3><<<gS, 256, GEMM_SMEM_BYTES>>>(p_q, p_k, p_s, HW, HW, CH, sIC, sIC, sW, 0.0625f, nullptr, nullptr);

    // 4) softmax over j, bf16 in place
    softmax_rows<<<dim3(HW, BATCH), 256>>>(p_s);

    // 5) attn (transposed): atT[i][c] = sum_j P[i,j] V[c,j]
    dim3 gA(CH / 128, HW / 128, BATCH);
    mma_gemm<3><<<gA, 256, GEMM_SMEM_BYTES>>>(p_s, p_v, p_atT, HW, CH, HW, sW, sCI, sIC, 1.0f, nullptr, nullptr);

    // 6) proj + bias + residual -> d_out
    dim3 gP(HW / 128, CH / 128, BATCH);
    mma_gemm<4><<<gP, 256, GEMM_SMEM_BYTES>>>(p_w16 + 3 * CH * CH, p_atT, out, CH, HW, CH, 0, sIC, sCI, 1.0f, bp, x);
}